// round 4
// baseline (speedup 1.0000x reference)
#include <cuda_runtime.h>
#include <math.h>

#define D_NODE 256
#define D_IN   128
#define HID    256
#define D_EDGE 272
#define EAF    16
#define NCLS   3
#define MAXN   65536
#define TILE   64

// 32 MB scratch for node features (allowed: __device__ global array)
__device__ float g_hnode[(size_t)MAXN * D_IN];
__device__ int   g_is64;

// ---------------- f32x2 helpers (Blackwell packed fp32 FMA) ----------------
__device__ __forceinline__ unsigned long long pack2(float a) {
    unsigned long long r;
    asm("mov.b64 %0, {%1, %1};" : "=l"(r) : "f"(a));
    return r;
}
__device__ __forceinline__ void fma2(unsigned long long& d,
                                     unsigned long long a, unsigned long long b) {
    asm("fma.rn.f32x2 %0, %1, %2, %0;" : "+l"(d) : "l"(a), "l"(b));
}
__device__ __forceinline__ float2 unpack2(unsigned long long v) {
    float2 r;
    asm("mov.b64 {%0, %1}, %2;" : "=f"(r.x), "=f"(r.y) : "l"(v));
    return r;
}
__device__ __forceinline__ float lrelu(float v) { return v >= 0.f ? v : 0.01f * v; }

// ---------------- edge_index dtype detection (int64 vs int32) --------------
// If stored as int64 (values < 2^31), every odd int32 word is 0.
// For genuine int32 data, 128 consecutive odd-position node ids all being 0
// has probability ~ (1/65536)^128 ~ 0.
__global__ void detect_idx64_kernel(const int* __restrict__ ei) {
    if (threadIdx.x == 0) {
        int allzero = 1;
        for (int i = 1; i < 256; i += 2)
            if (ei[i] != 0) { allzero = 0; break; }
        g_is64 = allzero;
    }
}

// ---------------- node MLP: h_node = leaky(x @ Wx + bx) --------------------
// Tile: M=64 nodes, N=128, K=256. 256 threads as 16x16; thread tile 4x8.
#define NODE_SMEM ((64 * 260 + 16 * 128) * 4)

__global__ __launch_bounds__(256, 1)
void node_mlp_kernel(const float* __restrict__ x, const float* __restrict__ Wx,
                     const float* __restrict__ bx, int N)
{
    extern __shared__ float smem[];
    float* sX = smem;              // 64 x 260 (padded stride)
    float* sW = smem + 64 * 260;   // 16 x 128

    const int tid = threadIdx.x;
    const int tx = tid & 15, ty = tid >> 4;
    const int m0 = blockIdx.x * TILE;

    // stage X tile: 64 rows x 256 floats
    {
        int e = tid >> 2, p = tid & 3;
        int r = m0 + e; if (r >= N) r = N - 1;
        const float4* src = (const float4*)(x + (size_t)r * D_NODE) + p * 16;
        float4* dst = (float4*)(sX + e * 260) + p * 16;
        #pragma unroll
        for (int j = 0; j < 16; j++) dst[j] = src[j];
    }

    const int krow = tid >> 4, seg = tid & 15;   // W chunk: 16x128, 8 floats/thread
    const float4* gsrc = (const float4*)(Wx + krow * D_IN + seg * 8);
    float4 p0 = gsrc[0], p1 = gsrc[1];

    unsigned long long acc[4][4];
    #pragma unroll
    for (int i = 0; i < 4; i++)
        #pragma unroll
        for (int j = 0; j < 4; j++) acc[i][j] = 0ull;

    const float* aBase = sX + (ty * 4) * 260;

    #pragma unroll 1
    for (int c = 0; c < 16; c++) {
        __syncthreads();
        float4* wd = (float4*)(sW + krow * D_IN + seg * 8);
        wd[0] = p0; wd[1] = p1;
        __syncthreads();
        if (c < 15) { const float4* g2 = gsrc + (size_t)(c + 1) * 512; p0 = g2[0]; p1 = g2[1]; }
        const float* aP = aBase + c * 16;
        #pragma unroll
        for (int kk = 0; kk < 16; kk++) {
            unsigned long long a0 = pack2(aP[kk]);
            unsigned long long a1 = pack2(aP[260 + kk]);
            unsigned long long a2 = pack2(aP[520 + kk]);
            unsigned long long a3 = pack2(aP[780 + kk]);
            const float* wrow = sW + kk * D_IN + tx * 4;
            #pragma unroll
            for (int g = 0; g < 2; g++) {
                ulonglong2 w = *(const ulonglong2*)(wrow + g * 64);
                fma2(acc[0][2*g], a0, w.x); fma2(acc[0][2*g+1], a0, w.y);
                fma2(acc[1][2*g], a1, w.x); fma2(acc[1][2*g+1], a1, w.y);
                fma2(acc[2][2*g], a2, w.x); fma2(acc[2][2*g+1], a2, w.y);
                fma2(acc[3][2*g], a3, w.x); fma2(acc[3][2*g+1], a3, w.y);
            }
        }
    }

    #pragma unroll
    for (int g = 0; g < 2; g++) {
        float4 bias = *(const float4*)(bx + tx * 4 + g * 64);
        #pragma unroll
        for (int i = 0; i < 4; i++) {
            int r = m0 + ty * 4 + i;
            if (r < N) {
                float2 u0 = unpack2(acc[i][2*g]);
                float2 u1 = unpack2(acc[i][2*g+1]);
                float4 v = make_float4(lrelu(u0.x + bias.x), lrelu(u0.y + bias.y),
                                       lrelu(u1.x + bias.z), lrelu(u1.y + bias.w));
                *(float4*)(g_hnode + (size_t)r * D_IN + tx * 4 + g * 64) = v;
            }
        }
    }
}

// ---------------- fused edge pipeline ---------------------------------------
// SMEM layout (floats):
//   sEF  : 64 x 276   (ef tile, K=272 used)          off 0
//   sH0  : 64 x 260                                  off 17664
//   sH1  : 64 x 260                                  off 34304
//   sW   : 16 x 256   (weight chunk stage)           off 50944
//   sWl  : 256 x 3                                   off 55040
//   sLog : 64 x 3                                    off 55808
//   sIds : 128 ints                                  off 56000
#define EDGE_SMEM (56128 * 4)

// One GEMM layer: sOut[64,256] = leaky(sA[64,K] @ Wg[K,256] + bg), sOut stride 260.
template<int K, int LDA>
__device__ __forceinline__ void gemm_hid(const float* __restrict__ sA,
                                         float* __restrict__ sW,
                                         const float* __restrict__ Wg,
                                         const float* __restrict__ bg,
                                         float* __restrict__ sOut,
                                         int tx, int ty, int tid)
{
    constexpr int NCH = K / 16;
    const int krow = tid >> 4, seg = tid & 15;   // chunk 16x256, 16 floats/thread
    const float4* gsrc = (const float4*)(Wg + krow * HID + seg * 16);
    float4 p0 = gsrc[0], p1 = gsrc[1], p2 = gsrc[2], p3 = gsrc[3];

    unsigned long long acc[4][8];
    #pragma unroll
    for (int i = 0; i < 4; i++)
        #pragma unroll
        for (int j = 0; j < 8; j++) acc[i][j] = 0ull;

    const float* aBase = sA + (ty * 4) * LDA;

    #pragma unroll 1
    for (int c = 0; c < NCH; c++) {
        __syncthreads();
        float4* wd = (float4*)(sW + krow * HID + seg * 16);
        wd[0] = p0; wd[1] = p1; wd[2] = p2; wd[3] = p3;
        __syncthreads();
        if (c + 1 < NCH) {
            const float4* g2 = gsrc + (size_t)(c + 1) * 1024;
            p0 = g2[0]; p1 = g2[1]; p2 = g2[2]; p3 = g2[3];
        }
        const float* aP = aBase + c * 16;
        #pragma unroll
        for (int kk = 0; kk < 16; kk++) {
            unsigned long long a0 = pack2(aP[kk]);
            unsigned long long a1 = pack2(aP[LDA + kk]);
            unsigned long long a2 = pack2(aP[2 * LDA + kk]);
            unsigned long long a3 = pack2(aP[3 * LDA + kk]);
            const float* wrow = sW + kk * HID + tx * 4;
            #pragma unroll
            for (int g = 0; g < 4; g++) {
                ulonglong2 w = *(const ulonglong2*)(wrow + g * 64);
                fma2(acc[0][2*g], a0, w.x); fma2(acc[0][2*g+1], a0, w.y);
                fma2(acc[1][2*g], a1, w.x); fma2(acc[1][2*g+1], a1, w.y);
                fma2(acc[2][2*g], a2, w.x); fma2(acc[2][2*g+1], a2, w.y);
                fma2(acc[3][2*g], a3, w.x); fma2(acc[3][2*g+1], a3, w.y);
            }
        }
    }

    #pragma unroll
    for (int g = 0; g < 4; g++) {
        float4 bias = *(const float4*)(bg + tx * 4 + g * 64);
        #pragma unroll
        for (int i = 0; i < 4; i++) {
            float2 u0 = unpack2(acc[i][2*g]);
            float2 u1 = unpack2(acc[i][2*g+1]);
            float4 v = make_float4(lrelu(u0.x + bias.x), lrelu(u0.y + bias.y),
                                   lrelu(u1.x + bias.z), lrelu(u1.y + bias.w));
            *(float4*)(sOut + (ty * 4 + i) * 260 + tx * 4 + g * 64) = v;
        }
    }
}

__global__ __launch_bounds__(256, 1)
void edge_net_kernel(const int* __restrict__ eidx, const float* __restrict__ eattr,
                     const float* __restrict__ W0, const float* __restrict__ b0,
                     const float* __restrict__ Wm, const float* __restrict__ bm,
                     const float* __restrict__ Wl, const float* __restrict__ bl,
                     float* __restrict__ out, int E)
{
    extern __shared__ float smem[];
    float* sEF  = smem;
    float* sH0  = smem + 17664;
    float* sH1  = smem + 34304;
    float* sW   = smem + 50944;
    float* sWl  = smem + 55040;
    float* sLog = smem + 55808;
    int*   sIds = (int*)(smem + 56000);

    const int tid = threadIdx.x;
    const int tx = tid & 15, ty = tid >> 4;
    const int e0 = blockIdx.x * TILE;
    const int is64 = g_is64;

    // load edge ids (row then col) + stage Wlast
    if (tid < 128) {
        int which = tid >> 6;           // 0 = row, 1 = col
        int e = tid & 63;
        int ge = e0 + e; if (ge >= E) ge = E - 1;
        int idx = which == 0 ? ge : (E + ge);
        sIds[tid] = is64 ? eidx[2 * idx] : eidx[idx];
    }
    if (tid < 192) ((float4*)sWl)[tid] = ((const float4*)Wl)[tid];
    __syncthreads();

    // gather ef = [h_node[row] | h_node[col] | edge_attr]  (68 float4 per edge)
    {
        int e = tid >> 2, p = tid & 3;
        int ge = e0 + e; if (ge >= E) ge = E - 1;
        int rn = sIds[e];
        int cn = sIds[64 + e];
        const float4* hr = (const float4*)(g_hnode + (size_t)rn * D_IN);
        const float4* hc = (const float4*)(g_hnode + (size_t)cn * D_IN);
        const float4* ea = (const float4*)(eattr + (size_t)ge * EAF);
        float4* dst = (float4*)(sEF + e * 276);
        #pragma unroll
        for (int j = 0; j < 17; j++) {
            int fi = p * 17 + j;
            float4 v;
            if (fi < 32)      v = hr[fi];
            else if (fi < 64) v = hc[fi - 32];
            else              v = ea[fi - 64];
            dst[fi] = v;
        }
    }
    // first __syncthreads inside gemm_hid covers gather completion

    // layer 0: 272 -> 256
    gemm_hid<D_EDGE, 276>(sEF, sW, W0, b0, sH0, tx, ty, tid);

    // 8 mid layers: 256 -> 256 (ping-pong; ends in sH0)
    float* a = sH0;
    float* b = sH1;
    #pragma unroll 1
    for (int l = 0; l < 8; l++) {
        gemm_hid<HID, 260>(a, sW, Wm + (size_t)l * HID * HID, bm + l * HID, b, tx, ty, tid);
        float* t = a; a = b; b = t;
    }
    __syncthreads();   // all rows of final hidden visible

    // last layer: logits[64,3] = a @ Wlast + blast
    if (tid < 192) {
        int e = tid / 3, c = tid - 3 * (tid / 3);
        float accv = bl[c];
        const float* hrow = a + e * 260;
        #pragma unroll 8
        for (int k = 0; k < HID; k++)
            accv = fmaf(hrow[k], sWl[k * 3 + c], accv);
        sLog[e * 3 + c] = accv;
    }
    __syncthreads();

    // log_softmax + store
    if (tid < 64) {
        int ge = e0 + tid;
        if (ge < E) {
            float l0 = sLog[tid * 3], l1 = sLog[tid * 3 + 1], l2 = sLog[tid * 3 + 2];
            float m = fmaxf(l0, fmaxf(l1, l2));
            float s = expf(l0 - m) + expf(l1 - m) + expf(l2 - m);
            float lse = m + logf(s);
            out[(size_t)ge * 3 + 0] = l0 - lse;
            out[(size_t)ge * 3 + 1] = l1 - lse;
            out[(size_t)ge * 3 + 2] = l2 - lse;
        }
    }
}

// ---------------- launch -----------------------------------------------------
extern "C" void kernel_launch(void* const* d_in, const int* in_sizes, int n_in,
                              void* d_out, int out_size)
{
    const float* x  = (const float*)d_in[0];
    const int*   ei = (const int*)d_in[1];       // int32 view; width detected at runtime
    const float* ea = (const float*)d_in[2];
    const float* Wx = (const float*)d_in[3];
    const float* bx = (const float*)d_in[4];
    const float* W0 = (const float*)d_in[5];
    const float* b0 = (const float*)d_in[6];
    const float* Wm = (const float*)d_in[7];
    const float* bm = (const float*)d_in[8];
    const float* Wl = (const float*)d_in[9];
    const float* bl = (const float*)d_in[10];
    float* out = (float*)d_out;

    const int N = in_sizes[0] / D_NODE;
    const int E = in_sizes[2] / EAF;

    cudaFuncSetAttribute(node_mlp_kernel,
                         cudaFuncAttributeMaxDynamicSharedMemorySize, NODE_SMEM);
    cudaFuncSetAttribute(edge_net_kernel,
                         cudaFuncAttributeMaxDynamicSharedMemorySize, EDGE_SMEM);

    detect_idx64_kernel<<<1, 32>>>(ei);
    node_mlp_kernel<<<(N + TILE - 1) / TILE, 256, NODE_SMEM>>>(x, Wx, bx, N);
    edge_net_kernel<<<(E + TILE - 1) / TILE, 256, EDGE_SMEM>>>(
        ei, ea, W0, b0, Wm, bm, Wl, bl, out, E);
}